// round 8
// baseline (speedup 1.0000x reference)
#include <cuda_runtime.h>
#include <math.h>

// Problem constants
#define BB 512
#define TT 512
#define II 8
#define HH 256

// Partitioning: 8 batch tiles x 16 h-column tiles = 128 CTAs (single wave)
#define NBT 8
#define NCT 16
#define BT 64          // batch rows per CTA
#define CT 16          // h columns per CTA (=> 48 gh columns: r,z,n)
#define NCTAS (NBT * NCT)
#define NTHREADS 512

// SMEM pitches in float4
#define WS_PITCH 65
#define HS_PITCH 65
#define WIH_PITCH 10   // floats; even => 8B-aligned u64 pairs

// Persistent device state
__device__ float g_h[2][BB][HH];
__device__ unsigned g_bar_count = 0;
__device__ unsigned g_bar_gen = 0;
// One monotonic counter per batch tile (padded to its own 128B line).
// Zero-initialized at module load; reset to 0 at end of every launch.
__device__ unsigned g_tile_cnt[NBT][32];

__device__ __forceinline__ void grid_barrier() {   // used ONCE (after init)
    __syncthreads();
    if (threadIdx.x == 0) {
        __threadfence();
        volatile unsigned* vgen = (volatile unsigned*)&g_bar_gen;
        unsigned gen = *vgen;
        unsigned arrived = atomicAdd(&g_bar_count, 1u);
        if (arrived == NCTAS - 1u) {
            *((volatile unsigned*)&g_bar_count) = 0u;
            __threadfence();
            *vgen = gen + 1u;
        } else {
            while (*vgen == gen) { }
        }
        __threadfence();
    }
    __syncthreads();
}

__device__ __forceinline__ unsigned ld_acq_gpu(const unsigned* p) {
    unsigned v;
    asm volatile("ld.acquire.gpu.u32 %0, [%1];" : "=r"(v) : "l"(p) : "memory");
    return v;
}

__device__ __forceinline__ float sigmoidf_fast(float v) {
    return 1.0f / (1.0f + __expf(-v));
}

__device__ __forceinline__ float tanh_fast(float v) {
    v = fminf(fmaxf(v, -15.0f), 15.0f);
    float e = __expf(-2.0f * v);
    return __fdividef(1.0f - e, 1.0f + e);
}

// Blackwell packed dual-fp32 FMA
__device__ __forceinline__ void ffma2(unsigned long long& d,
                                      unsigned long long a,
                                      unsigned long long b) {
    asm("fma.rn.f32x2 %0, %1, %2, %0;" : "+l"(d) : "l"(a), "l"(b));
}

__device__ __forceinline__ float f2sum(unsigned long long v) {
    return __uint_as_float((unsigned)v) + __uint_as_float((unsigned)(v >> 32));
}

// One 16-k4 GEMM chunk (2 batch rows x 3 gates per thread)
#define CHUNK(CBASE, WAITN)                                                   \
  {                                                                           \
    asm volatile("cp.async.wait_group " #WAITN ";" ::: "memory");             \
    __syncthreads();                                                          \
    _Pragma("unroll 4")                                                       \
    for (int kk = 0; kk < 16; kk++) {                                         \
      const int k4 = (CBASE) + kk;                                            \
      ulonglong2 w0 = w0q[k4], w1 = w1q[k4], w2 = w2q[k4];                    \
      ulonglong2 h0 = hq0[k4], h1 = hq1[k4];                                  \
      ffma2(acc0[0], h0.x, w0.x); ffma2(acc0[0], h0.y, w0.y);                 \
      ffma2(acc1[0], h0.x, w1.x); ffma2(acc1[0], h0.y, w1.y);                 \
      ffma2(acc2[0], h0.x, w2.x); ffma2(acc2[0], h0.y, w2.y);                 \
      ffma2(acc0[1], h1.x, w0.x); ffma2(acc0[1], h1.y, w0.y);                 \
      ffma2(acc1[1], h1.x, w1.x); ffma2(acc1[1], h1.y, w1.y);                 \
      ffma2(acc2[1], h1.x, w2.x); ffma2(acc2[1], h1.y, w2.y);                 \
    }                                                                         \
  }

__global__ void __launch_bounds__(NTHREADS, 1)
gru_persistent_kernel(const float* __restrict__ x,
                      const float* __restrict__ W_ih,
                      const float* __restrict__ W_hh,
                      const float* __restrict__ b_ih,
                      const float* __restrict__ b_hh,
                      const float* __restrict__ W_lin,
                      const float* __restrict__ b_lin,
                      float* __restrict__ out)
{
    extern __shared__ char smem_raw[];
    float4* ws4 = (float4*)smem_raw;                 // [48][WS_PITCH]
    float4* hs4 = ws4 + 48 * WS_PITCH;               // [64][HS_PITCH]
    float*  wlin256 = (float*)(hs4 + 64 * HS_PITCH); // [256] full W_lin (16B aligned)
    float*  wih  = wlin256 + 256;                    // [48][WIH_PITCH]
    float*  xs   = wih + 48 * WIH_PITCH;             // [64][8]
    float*  bihs = xs + 64 * 8;                      // [48]
    float*  bhhs = bihs + 48;                        // [48]

    const int tid = threadIdx.x;
    const int cta = blockIdx.x;
    const int bt  = cta / NCT;
    const int ct  = cta % NCT;
    const int b0  = bt * BT;
    const int j0  = ct * CT;
    unsigned* cnt = &g_tile_cnt[bt][0];
    const float blin = __ldg(&b_lin[0]);

    // ---- one-time: weight slices into SMEM ----
    {
        const float4* whh4 = (const float4*)W_hh;
        for (int idx = tid; idx < 48 * 64; idx += NTHREADS) {
            int c = idx >> 6, k4 = idx & 63;
            int g = c >> 4, l = c & 15;
            int grow = g * HH + j0 + l;
            ws4[c * WS_PITCH + k4] = whh4[grow * (HH / 4) + k4];
        }
        for (int idx = tid; idx < 48 * WIH_PITCH; idx += NTHREADS) {
            int c = idx / WIH_PITCH, k = idx % WIH_PITCH;
            int g = c >> 4, l = c & 15;
            int grow = g * HH + j0 + l;
            wih[idx] = (k < II) ? W_ih[grow * II + k] : 0.0f;
        }
        if (tid < 48) {
            int g = tid >> 4, l = tid & 15;
            int grow = g * HH + j0 + l;
            bihs[tid] = b_ih[grow];
            bhhs[tid] = b_hh[grow];
        }
        if (tid < 256) wlin256[tid] = W_lin[tid];
    }

    // ---- one-time: h0 = 0 ----
    {
        float* h0 = &g_h[0][0][0];
        const int perH = (BB * HH) / NCTAS;          // 1024
        for (int i = tid; i < perH; i += NTHREADS) h0[cta * perH + i] = 0.0f;
    }

    grid_barrier();   // once: h0 visible chip-wide; tile counters are 0

    const int ty = tid >> 4;                         // 0..31 -> 2 batch rows
    const int tx = tid & 15;                         // 0..15 -> 1 h-col (x3 gates)
    const int r0 = 2 * ty;

    const ulonglong2* w0q = (const ulonglong2*)(ws4 + tx * WS_PITCH);
    const ulonglong2* w1q = (const ulonglong2*)(ws4 + (16 + tx) * WS_PITCH);
    const ulonglong2* w2q = (const ulonglong2*)(ws4 + (32 + tx) * WS_PITCH);
    const ulonglong2* hq0 = (const ulonglong2*)(hs4 + r0 * HS_PITCH);
    const ulonglong2* hq1 = (const ulonglong2*)(hs4 + (r0 + 1) * HS_PITCH);

    const unsigned long long* wxr = (const unsigned long long*)&wih[tx * WIH_PITCH];
    const unsigned long long* wxz = (const unsigned long long*)&wih[(16 + tx) * WIH_PITCH];
    const unsigned long long* wxn = (const unsigned long long*)&wih[(32 + tx) * WIH_PITCH];

    for (int t = 0; t < TT; t++) {
        const int p = t & 1;

        // ---- tile-scope sync: h_t (written by the 16 CTAs of this batch
        // tile at iteration t-1) must be visible. Also orders SMEM reuse:
        // all threads passed last iteration's gate phase before we overwrite
        // xs / hs4 below.
        if (tid == 0) {
            const unsigned target = 16u * (unsigned)t;
            while (ld_acq_gpu(cnt) < target) { }
        }
        __syncthreads();

        // ---- async h-tile fetch: 4 chunks x 16KB via cp.async.cg ----
        const float4* hsrc = (const float4*)&g_h[p][b0][0];
        #pragma unroll
        for (int c = 0; c < 4; c++) {
            #pragma unroll
            for (int u = 0; u < 2; u++) {
                int idx = u * NTHREADS + tid;        // 0..1023
                int r = idx >> 4;
                int k4 = (idx & 15) + c * 16;
                unsigned dst = (unsigned)__cvta_generic_to_shared(
                                   &hs4[r * HS_PITCH + k4]);
                const float4* src = hsrc + r * 64 + k4;
                asm volatile("cp.async.cg.shared.global [%0], [%1], 16;"
                             :: "r"(dst), "l"(src) : "memory");
            }
            asm volatile("cp.async.commit_group;" ::: "memory");
        }

        // x_t tile [64][8]
        if (tid < BT * 2) {
            int r = tid >> 1, half = tid & 1;
            const float4* xsrc = (const float4*)&x[((size_t)(b0 + r) * TT + t) * II];
            ((float4*)xs)[r * 2 + half] = __ldg(&xsrc[half]);
        }

        // ---- GEMM over h tile ----
        unsigned long long acc0[2], acc1[2], acc2[2];
        acc0[0] = acc0[1] = acc1[0] = acc1[1] = acc2[0] = acc2[1] = 0ull;

        CHUNK(0, 3)
        CHUNK(16, 2)
        CHUNK(32, 1)
        CHUNK(48, 0)

        // ---- pred[t-1] from the full h_t tile (ct==0 CTA only; off the
        // critical path of the other 15 CTAs; no atomics, no contention) ----
        if (ct == 0 && t > 0) {
            const int row = tid >> 3;                // 0..63
            const int oct = tid & 7;                 // 0..7 -> 32 cols each
            const ulonglong2* hrq =
                (const ulonglong2*)(hs4 + row * HS_PITCH);
            const ulonglong2* wlq = (const ulonglong2*)wlin256;
            unsigned long long a = 0ull;
            #pragma unroll
            for (int q = 0; q < 8; q++) {
                ulonglong2 hv = hrq[oct * 8 + q];
                ulonglong2 wv = wlq[oct * 8 + q];
                ffma2(a, hv.x, wv.x);
                ffma2(a, hv.y, wv.y);
            }
            float v = f2sum(a);
            v += __shfl_xor_sync(0xffffffffu, v, 1);
            v += __shfl_xor_sync(0xffffffffu, v, 2);
            v += __shfl_xor_sync(0xffffffffu, v, 4);
            if (oct == 0)
                out[(size_t)(b0 + row) * TT + (t - 1)] = v + blin;
        }

        // ---- fused gates + h update ----
        #pragma unroll
        for (int i = 0; i < 2; i++) {
            const int r = r0 + i;
            const unsigned long long* xq =
                (const unsigned long long*)&xs[r * II];
            unsigned long long ar = 0ull, az = 0ull, an = 0ull;
            #pragma unroll
            for (int kq = 0; kq < 4; kq++) {
                unsigned long long xv = xq[kq];
                ffma2(ar, xv, wxr[kq]);
                ffma2(az, xv, wxz[kq]);
                ffma2(an, xv, wxn[kq]);
            }
            float rr = sigmoidf_fast(bihs[tx] + f2sum(ar) + f2sum(acc0[i]) + bhhs[tx]);
            float zz = sigmoidf_fast(bihs[16 + tx] + f2sum(az) + f2sum(acc1[i]) + bhhs[16 + tx]);
            float nn = tanh_fast(bihs[32 + tx] + f2sum(an) +
                                 rr * (f2sum(acc2[i]) + bhhs[32 + tx]));
            float hold = ((const float*)hs4)[r * (HS_PITCH * 4) + j0 + tx];
            float hn = (1.0f - zz) * nn + zz * hold;
            __stcg(&g_h[1 - p][b0 + r][j0 + tx], hn);
        }

        // ---- publish: all threads' h stores done -> release-increment ----
        __syncthreads();
        if (tid == 0) {
            __threadfence();
            atomicAdd(cnt, 1u);
        }
    }

    // ---- epilogue: pred[TT-1] from final h, then reset tile counter ----
    if (ct == 0) {
        if (tid == 0) {
            while (ld_acq_gpu(cnt) < 16u * (unsigned)TT) { }
        }
        __syncthreads();
        const float4* hsrc = (const float4*)&g_h[TT & 1][b0][0];
        for (int idx = tid; idx < 64 * 64; idx += NTHREADS) {
            int r = idx >> 6, k4 = idx & 63;
            hs4[r * HS_PITCH + k4] = __ldcg(&hsrc[r * 64 + k4]);
        }
        __syncthreads();
        {
            const int row = tid >> 3;
            const int oct = tid & 7;
            const ulonglong2* hrq =
                (const ulonglong2*)(hs4 + row * HS_PITCH);
            const ulonglong2* wlq = (const ulonglong2*)wlin256;
            unsigned long long a = 0ull;
            #pragma unroll
            for (int q = 0; q < 8; q++) {
                ulonglong2 hv = hrq[oct * 8 + q];
                ulonglong2 wv = wlq[oct * 8 + q];
                ffma2(a, hv.x, wv.x);
                ffma2(a, hv.y, wv.y);
            }
            float v = f2sum(a);
            v += __shfl_xor_sync(0xffffffffu, v, 1);
            v += __shfl_xor_sync(0xffffffffu, v, 2);
            v += __shfl_xor_sync(0xffffffffu, v, 4);
            if (oct == 0)
                out[(size_t)(b0 + row) * TT + (TT - 1)] = v + blin;
        }
        __syncthreads();
        if (tid == 0) atomicExch(cnt, 0u);   // ready for next graph replay
    }
}

extern "C" void kernel_launch(void* const* d_in, const int* in_sizes, int n_in,
                              void* d_out, int out_size) {
    const float* x     = (const float*)d_in[0];
    const float* W_ih  = (const float*)d_in[1];
    const float* W_hh  = (const float*)d_in[2];
    const float* b_ih  = (const float*)d_in[3];
    const float* b_hh  = (const float*)d_in[4];
    const float* W_lin = (const float*)d_in[5];
    const float* b_lin = (const float*)d_in[6];
    float* out = (float*)d_out;

    size_t smem = (size_t)(48 * WS_PITCH + 64 * HS_PITCH) * sizeof(float4)
                + (size_t)(256 + 48 * WIH_PITCH + 64 * 8 + 48 + 48) * sizeof(float);

    cudaFuncSetAttribute(gru_persistent_kernel,
                         cudaFuncAttributeMaxDynamicSharedMemorySize, (int)smem);

    gru_persistent_kernel<<<NCTAS, NTHREADS, smem>>>(
        x, W_ih, W_hh, b_ih, b_hh, W_lin, b_lin, out);
}

// round 10
// speedup vs baseline: 1.3765x; 1.3765x over previous
#include <cuda_runtime.h>
#include <math.h>

// Problem constants
#define BB 512
#define TT 512
#define II 8
#define HH 256

// Partitioning: 8 batch tiles x 16 h-column tiles = 128 CTAs (single wave)
#define NBT 8
#define NCT 16
#define BT 64          // batch rows per CTA
#define CT 16          // h columns per CTA (=> 48 gh columns: r,z,n)
#define NCTAS (NBT * NCT)
#define NTHREADS 256   // 8 warps: W smem traffic = nwarps*49KB -> keep at 8!

// SMEM pitches in float4
#define WS_PITCH 65
#define HS_PITCH 65
#define WIH_PITCH 10   // floats; even => 8B-aligned u64 pairs

// Persistent device state
__device__ float g_h[2][BB][HH];
__device__ unsigned g_bar_count = 0;
__device__ unsigned g_bar_gen = 0;
// Per-CTA monotonic step flags, each on its own 128B line. Reset at end.
__device__ unsigned g_flag[NBT][NCT][32];

__device__ __forceinline__ void grid_barrier() {
    __syncthreads();
    if (threadIdx.x == 0) {
        __threadfence();
        volatile unsigned* vgen = (volatile unsigned*)&g_bar_gen;
        unsigned gen = *vgen;
        unsigned arrived = atomicAdd(&g_bar_count, 1u);
        if (arrived == NCTAS - 1u) {
            *((volatile unsigned*)&g_bar_count) = 0u;
            __threadfence();
            *vgen = gen + 1u;
        } else {
            while (*vgen == gen) { }
        }
        __threadfence();
    }
    __syncthreads();
}

__device__ __forceinline__ unsigned ld_acq_gpu(const unsigned* p) {
    unsigned v;
    asm volatile("ld.acquire.gpu.u32 %0, [%1];" : "=r"(v) : "l"(p) : "memory");
    return v;
}

__device__ __forceinline__ void st_rel_gpu(unsigned* p, unsigned v) {
    asm volatile("st.release.gpu.u32 [%0], %1;" :: "l"(p), "r"(v) : "memory");
}

__device__ __forceinline__ float sigmoidf_fast(float v) {
    return 1.0f / (1.0f + __expf(-v));
}

__device__ __forceinline__ float tanh_fast(float v) {
    v = fminf(fmaxf(v, -15.0f), 15.0f);
    float e = __expf(-2.0f * v);
    return __fdividef(1.0f - e, 1.0f + e);
}

// Blackwell packed dual-fp32 FMA
__device__ __forceinline__ void ffma2(unsigned long long& d,
                                      unsigned long long a,
                                      unsigned long long b) {
    asm("fma.rn.f32x2 %0, %1, %2, %0;" : "+l"(d) : "l"(a), "l"(b));
}

__device__ __forceinline__ float f2sum(unsigned long long v) {
    return __uint_as_float((unsigned)v) + __uint_as_float((unsigned)(v >> 32));
}

// Wait for the 4 producers of h-chunk c to have published step >= t.
#define WAITP(c)                                                              \
  do {                                                                        \
    if (tid < 4) {                                                            \
      const unsigned* f = &g_flag[bt][4 * (c) + tid][0];                      \
      while (ld_acq_gpu(f) < (unsigned)t) { }                                 \
    }                                                                         \
    __syncthreads();                                                          \
  } while (0)

// Issue cp.async for h-chunk c (64 rows x 16 k4 = 16KB)
#define ISSUE(c)                                                              \
  do {                                                                        \
    _Pragma("unroll")                                                         \
    for (int u = 0; u < 4; u++) {                                             \
      int idx = u * NTHREADS + tid;                                           \
      int r = idx >> 4;                                                       \
      int k4 = (idx & 15) + (c) * 16;                                         \
      unsigned dst = (unsigned)__cvta_generic_to_shared(                      \
                         &hs4[r * HS_PITCH + k4]);                            \
      const float4* src = hsrc + r * 64 + k4;                                 \
      asm volatile("cp.async.cg.shared.global [%0], [%1], 16;"                \
                   :: "r"(dst), "l"(src) : "memory");                         \
    }                                                                         \
    asm volatile("cp.async.commit_group;" ::: "memory");                      \
  } while (0)

// One 16-k4 GEMM chunk (4 batch rows x 3 gates per thread)
#define CHUNK(CBASE, WAITN)                                                   \
  {                                                                           \
    asm volatile("cp.async.wait_group " #WAITN ";" ::: "memory");             \
    __syncthreads();                                                          \
    _Pragma("unroll 4")                                                       \
    for (int kk = 0; kk < 16; kk++) {                                         \
      const int k4 = (CBASE) + kk;                                            \
      ulonglong2 w0 = w0q[k4], w1 = w1q[k4], w2 = w2q[k4];                    \
      _Pragma("unroll")                                                       \
      for (int i = 0; i < 4; i++) {                                           \
        ulonglong2 hv = hq[i][k4];                                            \
        ffma2(acc0[i], hv.x, w0.x); ffma2(acc0[i], hv.y, w0.y);               \
        ffma2(acc1[i], hv.x, w1.x); ffma2(acc1[i], hv.y, w1.y);               \
        ffma2(acc2[i], hv.x, w2.x); ffma2(acc2[i], hv.y, w2.y);               \
      }                                                                       \
    }                                                                         \
  }

// Full-row pred dot: 4 octs x 16 ulonglong2 = 64 x 16B = all 256 columns.
// (R9 bug: used 8 per oct -> only 128 columns.)
#define PRED_DOT(a, hrq, wlq, oct)                                            \
  do {                                                                        \
    _Pragma("unroll")                                                         \
    for (int q = 0; q < 16; q++) {                                            \
      ulonglong2 hv = (hrq)[(oct) * 16 + q];                                  \
      ulonglong2 wv = (wlq)[(oct) * 16 + q];                                  \
      ffma2(a, hv.x, wv.x);                                                   \
      ffma2(a, hv.y, wv.y);                                                   \
    }                                                                         \
  } while (0)

__global__ void __launch_bounds__(NTHREADS, 1)
gru_persistent_kernel(const float* __restrict__ x,
                      const float* __restrict__ W_ih,
                      const float* __restrict__ W_hh,
                      const float* __restrict__ b_ih,
                      const float* __restrict__ b_hh,
                      const float* __restrict__ W_lin,
                      const float* __restrict__ b_lin,
                      float* __restrict__ out)
{
    extern __shared__ char smem_raw[];
    float4* ws4 = (float4*)smem_raw;                 // [48][WS_PITCH]
    float4* hs4 = ws4 + 48 * WS_PITCH;               // [64][HS_PITCH]
    float*  wlin256 = (float*)(hs4 + 64 * HS_PITCH); // [256] full W_lin
    float*  wih  = wlin256 + 256;                    // [48][WIH_PITCH]
    float*  xs   = wih + 48 * WIH_PITCH;             // [64][8]
    float*  bihs = xs + 64 * 8;                      // [48]
    float*  bhhs = bihs + 48;                        // [48]

    const int tid = threadIdx.x;
    const int cta = blockIdx.x;
    const int bt  = cta / NCT;
    const int ct  = cta % NCT;
    const int b0  = bt * BT;
    const int j0  = ct * CT;
    const float blin = __ldg(&b_lin[0]);

    // ---- one-time: weight slices into SMEM ----
    {
        const float4* whh4 = (const float4*)W_hh;
        for (int idx = tid; idx < 48 * 64; idx += NTHREADS) {
            int c = idx >> 6, k4 = idx & 63;
            int g = c >> 4, l = c & 15;
            int grow = g * HH + j0 + l;
            ws4[c * WS_PITCH + k4] = whh4[grow * (HH / 4) + k4];
        }
        for (int idx = tid; idx < 48 * WIH_PITCH; idx += NTHREADS) {
            int c = idx / WIH_PITCH, k = idx % WIH_PITCH;
            int g = c >> 4, l = c & 15;
            int grow = g * HH + j0 + l;
            wih[idx] = (k < II) ? W_ih[grow * II + k] : 0.0f;
        }
        if (tid < 48) {
            int g = tid >> 4, l = tid & 15;
            int grow = g * HH + j0 + l;
            bihs[tid] = b_ih[grow];
            bhhs[tid] = b_hh[grow];
        }
        if (tid < 256) wlin256[tid] = W_lin[tid];
    }

    // ---- one-time: h0 = 0 ----
    {
        float* h0 = &g_h[0][0][0];
        const int perH = (BB * HH) / NCTAS;          // 1024
        for (int i = tid; i < perH; i += NTHREADS) h0[cta * perH + i] = 0.0f;
    }

    grid_barrier();   // h0 visible chip-wide; flags are 0

    const int ty = tid >> 4;                         // 0..15 -> 4 batch rows
    const int tx = tid & 15;                         // 0..15 -> 1 h-col (x3 gates)
    const int r0 = 4 * ty;

    const ulonglong2* w0q = (const ulonglong2*)(ws4 + tx * WS_PITCH);
    const ulonglong2* w1q = (const ulonglong2*)(ws4 + (16 + tx) * WS_PITCH);
    const ulonglong2* w2q = (const ulonglong2*)(ws4 + (32 + tx) * WS_PITCH);
    const ulonglong2* hq[4];
    #pragma unroll
    for (int i = 0; i < 4; i++)
        hq[i] = (const ulonglong2*)(hs4 + (r0 + i) * HS_PITCH);

    const unsigned long long* wxr = (const unsigned long long*)&wih[tx * WIH_PITCH];
    const unsigned long long* wxz = (const unsigned long long*)&wih[(16 + tx) * WIH_PITCH];
    const unsigned long long* wxn = (const unsigned long long*)&wih[(32 + tx) * WIH_PITCH];

    for (int t = 0; t < TT; t++) {
        const int p = t & 1;
        const float4* hsrc = (const float4*)&g_h[p][b0][0];

        // x_t tile first (no cross-CTA dependency)
        if (tid < BT * 2) {
            int r = tid >> 1, half = tid & 1;
            const float4* xsrc = (const float4*)&x[((size_t)(b0 + r) * TT + t) * II];
            ((float4*)xs)[r * 2 + half] = __ldg(&xsrc[half]);
        }

        unsigned long long acc0[4], acc1[4], acc2[4];
        #pragma unroll
        for (int i = 0; i < 4; i++) { acc0[i] = 0ull; acc1[i] = 0ull; acc2[i] = 0ull; }

        // Interleaved: per-chunk producer waits absorb cross-CTA skew
        WAITP(0); ISSUE(0);
        WAITP(1); ISSUE(1);
        CHUNK(0, 1)
        WAITP(2); ISSUE(2);
        CHUNK(16, 1)
        WAITP(3); ISSUE(3);
        CHUNK(32, 1)
        CHUNK(48, 0)

        // ---- pred[t-1] from the full h_t tile (last CTA of the tile: its
        // delayed flag gates only chunk 3 of consumers -> absorbed) ----
        if (ct == NCT - 1 && t > 0) {
            const int row = tid >> 2;                // 0..63
            const int oct = tid & 3;                 // 0..3 -> 64 cols each
            const ulonglong2* hrq = (const ulonglong2*)(hs4 + row * HS_PITCH);
            const ulonglong2* wlq = (const ulonglong2*)wlin256;
            unsigned long long a = 0ull;
            PRED_DOT(a, hrq, wlq, oct);
            float v = f2sum(a);
            v += __shfl_xor_sync(0xffffffffu, v, 1);
            v += __shfl_xor_sync(0xffffffffu, v, 2);
            if (oct == 0)
                out[(size_t)(b0 + row) * TT + (t - 1)] = v + blin;
        }

        // ---- fused gates + h update ----
        #pragma unroll
        for (int i = 0; i < 4; i++) {
            const int r = r0 + i;
            const unsigned long long* xq = (const unsigned long long*)&xs[r * II];
            unsigned long long ar = 0ull, az = 0ull, an = 0ull;
            #pragma unroll
            for (int kq = 0; kq < 4; kq++) {
                unsigned long long xv = xq[kq];
                ffma2(ar, xv, wxr[kq]);
                ffma2(az, xv, wxz[kq]);
                ffma2(an, xv, wxn[kq]);
            }
            float rr = sigmoidf_fast(bihs[tx] + f2sum(ar) + f2sum(acc0[i]) + bhhs[tx]);
            float zz = sigmoidf_fast(bihs[16 + tx] + f2sum(az) + f2sum(acc1[i]) + bhhs[16 + tx]);
            float nn = tanh_fast(bihs[32 + tx] + f2sum(an) +
                                 rr * (f2sum(acc2[i]) + bhhs[32 + tx]));
            float hold = ((const float*)hs4)[r * (HS_PITCH * 4) + j0 + tx];
            float hn = (1.0f - zz) * nn + zz * hold;
            __stcg(&g_h[1 - p][b0 + r][j0 + tx], hn);
        }

        // ---- publish step t+1-ready: release store (no atomics) ----
        __syncthreads();
        if (tid == 0) st_rel_gpu(&g_flag[bt][ct][0], (unsigned)(t + 1));
    }

    // ---- epilogue: pred[TT-1] on the pred CTA ----
    if (ct == NCT - 1) {
        if (tid < NCT) {
            const unsigned* f = &g_flag[bt][tid][0];
            while (ld_acq_gpu(f) < (unsigned)TT) { }
        }
        __syncthreads();
        const float4* hsrc = (const float4*)&g_h[TT & 1][b0][0];
        for (int idx = tid; idx < 64 * 64; idx += NTHREADS) {
            int r = idx >> 6, k4 = idx & 63;
            hs4[r * HS_PITCH + k4] = __ldcg(&hsrc[r * 64 + k4]);
        }
        __syncthreads();
        {
            const int row = tid >> 2;                // 0..63
            const int oct = tid & 3;                 // 0..3 -> 64 cols each
            const ulonglong2* hrq = (const ulonglong2*)(hs4 + row * HS_PITCH);
            const ulonglong2* wlq = (const ulonglong2*)wlin256;
            unsigned long long a = 0ull;
            PRED_DOT(a, hrq, wlq, oct);
            float v = f2sum(a);
            v += __shfl_xor_sync(0xffffffffu, v, 1);
            v += __shfl_xor_sync(0xffffffffu, v, 2);
            if (oct == 0)
                out[(size_t)(b0 + row) * TT + (TT - 1)] = v + blin;
        }
    }

    // ---- all CTAs done (pred CTA included), then reset own flag for the
    // next graph replay. Kernel boundary orders these resets vs next launch.
    grid_barrier();
    if (tid == 0) g_flag[bt][ct][0] = 0u;
}

extern "C" void kernel_launch(void* const* d_in, const int* in_sizes, int n_in,
                              void* d_out, int out_size) {
    const float* x     = (const float*)d_in[0];
    const float* W_ih  = (const float*)d_in[1];
    const float* W_hh  = (const float*)d_in[2];
    const float* b_ih  = (const float*)d_in[3];
    const float* b_hh  = (const float*)d_in[4];
    const float* W_lin = (const float*)d_in[5];
    const float* b_lin = (const float*)d_in[6];
    float* out = (float*)d_out;

    size_t smem = (size_t)(48 * WS_PITCH + 64 * HS_PITCH) * sizeof(float4)
                + (size_t)(256 + 48 * WIH_PITCH + 64 * 8 + 48 + 48) * sizeof(float);

    cudaFuncSetAttribute(gru_persistent_kernel,
                         cudaFuncAttributeMaxDynamicSharedMemorySize, (int)smem);

    gru_persistent_kernel<<<NCTAS, NTHREADS, smem>>>(
        x, W_ih, W_hh, b_ih, b_hh, W_lin, b_lin, out);
}

// round 11
// speedup vs baseline: 1.4692x; 1.0674x over previous
#include <cuda_runtime.h>
#include <math.h>

// Problem constants
#define BB 512
#define TT 512
#define II 8
#define HH 256

// Partitioning: 16 batch tiles x 16 h-column tiles = 256 CTAs, 2 CTAs/SM.
// The two co-resident CTAs on an SM come from different (independent) batch
// tiles -> one CTA's sync stalls overlap the other's compute.
#define NBT 16
#define NCT 16
#define BT 32          // batch rows per CTA
#define CT 16          // h columns per CTA (=> 48 gh columns: r,z,n)
#define NCTAS (NBT * NCT)
#define NTHREADS 128   // 4 warps; per-SM warp count unchanged (2 CTAs/SM)

// SMEM pitches in float4
#define WS_PITCH 65
#define HS_PITCH 65
#define WIH_PITCH 10   // floats; even => 8B-aligned u64 pairs

// Persistent device state
__device__ float g_h[2][BB][HH];
__device__ unsigned g_bar_count = 0;
__device__ unsigned g_bar_gen = 0;
// Per-CTA monotonic step flags, each on its own 128B line. Reset at end.
__device__ unsigned g_flag[NBT][NCT][32];

__device__ __forceinline__ void grid_barrier() {
    __syncthreads();
    if (threadIdx.x == 0) {
        __threadfence();
        volatile unsigned* vgen = (volatile unsigned*)&g_bar_gen;
        unsigned gen = *vgen;
        unsigned arrived = atomicAdd(&g_bar_count, 1u);
        if (arrived == NCTAS - 1u) {
            *((volatile unsigned*)&g_bar_count) = 0u;
            __threadfence();
            *vgen = gen + 1u;
        } else {
            while (*vgen == gen) { }
        }
        __threadfence();
    }
    __syncthreads();
}

__device__ __forceinline__ unsigned ld_acq_gpu(const unsigned* p) {
    unsigned v;
    asm volatile("ld.acquire.gpu.u32 %0, [%1];" : "=r"(v) : "l"(p) : "memory");
    return v;
}

__device__ __forceinline__ void st_rel_gpu(unsigned* p, unsigned v) {
    asm volatile("st.release.gpu.u32 [%0], %1;" :: "l"(p), "r"(v) : "memory");
}

__device__ __forceinline__ float sigmoidf_fast(float v) {
    return 1.0f / (1.0f + __expf(-v));
}

__device__ __forceinline__ float tanh_fast(float v) {
    v = fminf(fmaxf(v, -15.0f), 15.0f);
    float e = __expf(-2.0f * v);
    return __fdividef(1.0f - e, 1.0f + e);
}

// Blackwell packed dual-fp32 FMA
__device__ __forceinline__ void ffma2(unsigned long long& d,
                                      unsigned long long a,
                                      unsigned long long b) {
    asm("fma.rn.f32x2 %0, %1, %2, %0;" : "+l"(d) : "l"(a), "l"(b));
}

__device__ __forceinline__ float f2sum(unsigned long long v) {
    return __uint_as_float((unsigned)v) + __uint_as_float((unsigned)(v >> 32));
}

// Wait for the 4 producers of h-chunk c to have published step >= t.
#define WAITP(c)                                                              \
  do {                                                                        \
    if (tid < 4) {                                                            \
      const unsigned* f = &g_flag[bt][4 * (c) + tid][0];                      \
      while (ld_acq_gpu(f) < (unsigned)t) { }                                 \
    }                                                                         \
    __syncthreads();                                                          \
  } while (0)

// Issue cp.async for h-chunk c (32 rows x 16 k4 = 8KB)
#define ISSUE(c)                                                              \
  do {                                                                        \
    _Pragma("unroll")                                                         \
    for (int u = 0; u < 4; u++) {                                             \
      int idx = u * NTHREADS + tid;          /* 0..511 */                     \
      int r = idx >> 4;                      /* 0..31 */                      \
      int k4 = (idx & 15) + (c) * 16;                                         \
      unsigned dst = (unsigned)__cvta_generic_to_shared(                      \
                         &hs4[r * HS_PITCH + k4]);                            \
      const float4* src = hsrc + r * 64 + k4;                                 \
      asm volatile("cp.async.cg.shared.global [%0], [%1], 16;"                \
                   :: "r"(dst), "l"(src) : "memory");                         \
    }                                                                         \
    asm volatile("cp.async.commit_group;" ::: "memory");                      \
  } while (0)

// One 16-k4 GEMM chunk (4 batch rows x 3 gates per thread)
#define CHUNK(CBASE, WAITN)                                                   \
  {                                                                           \
    asm volatile("cp.async.wait_group " #WAITN ";" ::: "memory");             \
    __syncthreads();                                                          \
    _Pragma("unroll 4")                                                       \
    for (int kk = 0; kk < 16; kk++) {                                         \
      const int k4 = (CBASE) + kk;                                            \
      ulonglong2 w0 = w0q[k4], w1 = w1q[k4], w2 = w2q[k4];                    \
      _Pragma("unroll")                                                       \
      for (int i = 0; i < 4; i++) {                                           \
        ulonglong2 hv = hq[i][k4];                                            \
        ffma2(acc0[i], hv.x, w0.x); ffma2(acc0[i], hv.y, w0.y);               \
        ffma2(acc1[i], hv.x, w1.x); ffma2(acc1[i], hv.y, w1.y);               \
        ffma2(acc2[i], hv.x, w2.x); ffma2(acc2[i], hv.y, w2.y);               \
      }                                                                       \
    }                                                                         \
  }

// Full-row pred dot: 4 octs x 16 ulonglong2 = 64 x 16B = all 256 columns.
#define PRED_DOT(a, hrq, wlq, oct)                                            \
  do {                                                                        \
    _Pragma("unroll")                                                         \
    for (int q = 0; q < 16; q++) {                                            \
      ulonglong2 hv = (hrq)[(oct) * 16 + q];                                  \
      ulonglong2 wv = (wlq)[(oct) * 16 + q];                                  \
      ffma2(a, hv.x, wv.x);                                                   \
      ffma2(a, hv.y, wv.y);                                                   \
    }                                                                         \
  } while (0)

__global__ void __launch_bounds__(NTHREADS, 2)
gru_persistent_kernel(const float* __restrict__ x,
                      const float* __restrict__ W_ih,
                      const float* __restrict__ W_hh,
                      const float* __restrict__ b_ih,
                      const float* __restrict__ b_hh,
                      const float* __restrict__ W_lin,
                      const float* __restrict__ b_lin,
                      float* __restrict__ out)
{
    extern __shared__ char smem_raw[];
    float4* ws4 = (float4*)smem_raw;                 // [48][WS_PITCH]
    float4* hs4 = ws4 + 48 * WS_PITCH;               // [BT][HS_PITCH]
    float*  wlin256 = (float*)(hs4 + BT * HS_PITCH); // [256] full W_lin
    float*  wih  = wlin256 + 256;                    // [48][WIH_PITCH]
    float*  xs   = wih + 48 * WIH_PITCH;             // [BT][8]
    float*  bihs = xs + BT * 8;                      // [48]
    float*  bhhs = bihs + 48;                        // [48]

    const int tid = threadIdx.x;
    const int cta = blockIdx.x;
    const int bt  = cta >> 4;                        // 0..15
    const int ct  = cta & 15;                        // 0..15
    const int b0  = bt * BT;
    const int j0  = ct * CT;
    const float blin = __ldg(&b_lin[0]);

    // ---- one-time: weight slices into SMEM ----
    {
        const float4* whh4 = (const float4*)W_hh;
        for (int idx = tid; idx < 48 * 64; idx += NTHREADS) {
            int c = idx >> 6, k4 = idx & 63;
            int g = c >> 4, l = c & 15;
            int grow = g * HH + j0 + l;
            ws4[c * WS_PITCH + k4] = whh4[grow * (HH / 4) + k4];
        }
        for (int idx = tid; idx < 48 * WIH_PITCH; idx += NTHREADS) {
            int c = idx / WIH_PITCH, k = idx % WIH_PITCH;
            int g = c >> 4, l = c & 15;
            int grow = g * HH + j0 + l;
            wih[idx] = (k < II) ? W_ih[grow * II + k] : 0.0f;
        }
        if (tid < 48) {
            int g = tid >> 4, l = tid & 15;
            int grow = g * HH + j0 + l;
            bihs[tid] = b_ih[grow];
            bhhs[tid] = b_hh[grow];
        }
        for (int idx = tid; idx < 256; idx += NTHREADS) wlin256[idx] = W_lin[idx];
    }

    // ---- one-time: h0 = 0 ----
    {
        float* h0 = &g_h[0][0][0];
        const int perH = (BB * HH) / NCTAS;          // 512
        for (int i = tid; i < perH; i += NTHREADS) h0[cta * perH + i] = 0.0f;
    }

    grid_barrier();   // h0 visible chip-wide; flags are 0

    const int ty = tid >> 4;                         // 0..7 -> 4 batch rows
    const int tx = tid & 15;                         // 0..15 -> 1 h-col (x3 gates)
    const int r0 = 4 * ty;

    const ulonglong2* w0q = (const ulonglong2*)(ws4 + tx * WS_PITCH);
    const ulonglong2* w1q = (const ulonglong2*)(ws4 + (16 + tx) * WS_PITCH);
    const ulonglong2* w2q = (const ulonglong2*)(ws4 + (32 + tx) * WS_PITCH);
    const ulonglong2* hq[4];
    #pragma unroll
    for (int i = 0; i < 4; i++)
        hq[i] = (const ulonglong2*)(hs4 + (r0 + i) * HS_PITCH);

    const unsigned long long* wxr = (const unsigned long long*)&wih[tx * WIH_PITCH];
    const unsigned long long* wxz = (const unsigned long long*)&wih[(16 + tx) * WIH_PITCH];
    const unsigned long long* wxn = (const unsigned long long*)&wih[(32 + tx) * WIH_PITCH];

    // hold carried in registers: thread (ty,tx) computed h_t[r0+i][j0+tx]
    // at step t-1 itself; h0 = 0.
    float hreg[4] = {0.0f, 0.0f, 0.0f, 0.0f};

    for (int t = 0; t < TT; t++) {
        const int p = t & 1;
        const float4* hsrc = (const float4*)&g_h[p][b0][0];

        // x_t tile first (no cross-CTA dependency)
        if (tid < BT * 2) {
            int r = tid >> 1, half = tid & 1;
            const float4* xsrc = (const float4*)&x[((size_t)(b0 + r) * TT + t) * II];
            ((float4*)xs)[r * 2 + half] = __ldg(&xsrc[half]);
        }

        unsigned long long acc0[4], acc1[4], acc2[4];
        #pragma unroll
        for (int i = 0; i < 4; i++) { acc0[i] = 0ull; acc1[i] = 0ull; acc2[i] = 0ull; }

        // Interleaved: per-chunk producer waits absorb cross-CTA skew
        WAITP(0); ISSUE(0);
        WAITP(1); ISSUE(1);
        CHUNK(0, 1)
        WAITP(2); ISSUE(2);
        CHUNK(16, 1)
        WAITP(3); ISSUE(3);
        CHUNK(32, 1)
        CHUNK(48, 0)

        // ---- pred[t-1] from the full h_t tile (last CTA of the tile) ----
        if (ct == NCT - 1 && t > 0) {
            const int row = tid >> 2;                // 0..31
            const int oct = tid & 3;                 // 0..3 -> 64 cols each
            const ulonglong2* hrq = (const ulonglong2*)(hs4 + row * HS_PITCH);
            const ulonglong2* wlq = (const ulonglong2*)wlin256;
            unsigned long long a = 0ull;
            PRED_DOT(a, hrq, wlq, oct);
            float v = f2sum(a);
            v += __shfl_xor_sync(0xffffffffu, v, 1);
            v += __shfl_xor_sync(0xffffffffu, v, 2);
            if (oct == 0)
                out[(size_t)(b0 + row) * TT + (t - 1)] = v + blin;
        }

        // ---- fused gates + h update (hold from registers) ----
        #pragma unroll
        for (int i = 0; i < 4; i++) {
            const int r = r0 + i;
            const unsigned long long* xq = (const unsigned long long*)&xs[r * II];
            unsigned long long ar = 0ull, az = 0ull, an = 0ull;
            #pragma unroll
            for (int kq = 0; kq < 4; kq++) {
                unsigned long long xv = xq[kq];
                ffma2(ar, xv, wxr[kq]);
                ffma2(az, xv, wxz[kq]);
                ffma2(an, xv, wxn[kq]);
            }
            float rr = sigmoidf_fast(bihs[tx] + f2sum(ar) + f2sum(acc0[i]) + bhhs[tx]);
            float zz = sigmoidf_fast(bihs[16 + tx] + f2sum(az) + f2sum(acc1[i]) + bhhs[16 + tx]);
            float nn = tanh_fast(bihs[32 + tx] + f2sum(an) +
                                 rr * (f2sum(acc2[i]) + bhhs[32 + tx]));
            float hn = (1.0f - zz) * nn + zz * hreg[i];
            hreg[i] = hn;
            __stcg(&g_h[1 - p][b0 + r][j0 + tx], hn);
        }

        // ---- publish step t+1-ready: release store (no atomics) ----
        __syncthreads();
        if (tid == 0) st_rel_gpu(&g_flag[bt][ct][0], (unsigned)(t + 1));
    }

    // ---- epilogue: pred[TT-1] on the pred CTA ----
    if (ct == NCT - 1) {
        if (tid < NCT) {
            const unsigned* f = &g_flag[bt][tid][0];
            while (ld_acq_gpu(f) < (unsigned)TT) { }
        }
        __syncthreads();
        const float4* hsrc = (const float4*)&g_h[TT & 1][b0][0];
        for (int idx = tid; idx < BT * 64; idx += NTHREADS) {
            int r = idx >> 6, k4 = idx & 63;
            hs4[r * HS_PITCH + k4] = __ldcg(&hsrc[r * 64 + k4]);
        }
        __syncthreads();
        {
            const int row = tid >> 2;                // 0..31
            const int oct = tid & 3;                 // 0..3
            const ulonglong2* hrq = (const ulonglong2*)(hs4 + row * HS_PITCH);
            const ulonglong2* wlq = (const ulonglong2*)wlin256;
            unsigned long long a = 0ull;
            PRED_DOT(a, hrq, wlq, oct);
            float v = f2sum(a);
            v += __shfl_xor_sync(0xffffffffu, v, 1);
            v += __shfl_xor_sync(0xffffffffu, v, 2);
            if (oct == 0)
                out[(size_t)(b0 + row) * TT + (TT - 1)] = v + blin;
        }
    }

    // ---- all CTAs done, then reset own flag for the next graph replay ----
    grid_barrier();
    if (tid == 0) g_flag[bt][ct][0] = 0u;
}

extern "C" void kernel_launch(void* const* d_in, const int* in_sizes, int n_in,
                              void* d_out, int out_size) {
    const float* x     = (const float*)d_in[0];
    const float* W_ih  = (const float*)d_in[1];
    const float* W_hh  = (const float*)d_in[2];
    const float* b_ih  = (const float*)d_in[3];
    const float* b_hh  = (const float*)d_in[4];
    const float* W_lin = (const float*)d_in[5];
    const float* b_lin = (const float*)d_in[6];
    float* out = (float*)d_out;

    size_t smem = (size_t)(48 * WS_PITCH + BT * HS_PITCH) * sizeof(float4)
                + (size_t)(256 + 48 * WIH_PITCH + BT * 8 + 48 + 48) * sizeof(float);

    cudaFuncSetAttribute(gru_persistent_kernel,
                         cudaFuncAttributeMaxDynamicSharedMemorySize, (int)smem);

    gru_persistent_kernel<<<NCTAS, NTHREADS, smem>>>(
        x, W_ih, W_hh, b_ih, b_hh, W_lin, b_lin, out);
}